// round 7
// baseline (speedup 1.0000x reference)
#include <cuda_runtime.h>
#include <cuda_bf16.h>
#include <cstdint>

#define B_ 8
#define N_ 2048
#define D_ 128
#define ALPHA 0.2f
#define KT 64
#define NT (N_ / KT)        // 32 j-tiles
#define PSTR 72             // bf16 elems per smem row (64 + 8 pad) -> 144B stride
#define TILE_BYTES (128 * PSTR * 2)   // 18432 per buffer

// ---------------- scratch (device globals; no allocations allowed) ----------
__device__ __align__(16) float g_a1W[D_];
__device__ __align__(16) float g_a2W[D_];
__device__ __align__(16) float g_Wh1[B_ * N_];
__device__ __align__(16) float g_Wh2[B_ * N_];
__device__ __align__(16) __nv_bfloat16 g_WhT[(size_t)B_ * D_ * N_]; // [b][d][n] bf16, 4MB

// ---------------- K0: aW1[k] = sum_c W[k][c]*a[c],  aW2 with a[d:] ----------
__global__ void k0_wa(const float* __restrict__ W, const float* __restrict__ a) {
    int k = threadIdx.x;
    float s1 = 0.f, s2 = 0.f;
    for (int c = 0; c < D_; c++) {
        float wv = W[k * D_ + c];
        s1 = fmaf(wv, a[c], s1);
        s2 = fmaf(wv, a[D_ + c], s2);
    }
    g_a1W[k] = s1;
    g_a2W[k] = s2;
}

// ---------------- K1b: Wh1/Wh2 = h . (W a1/2), one warp per row ------------
__global__ void k1b_wh12(const float* __restrict__ h) {
    int gw = (blockIdx.x * blockDim.x + threadIdx.x) >> 5;
    int lane = threadIdx.x & 31;
    float4 hv = *(const float4*)(h + (size_t)gw * D_ + lane * 4);
    float4 a1 = *(const float4*)(g_a1W + lane * 4);
    float4 a2 = *(const float4*)(g_a2W + lane * 4);
    float s1 = hv.x * a1.x + hv.y * a1.y + hv.z * a1.z + hv.w * a1.w;
    float s2 = hv.x * a2.x + hv.y * a2.y + hv.z * a2.z + hv.w * a2.w;
#pragma unroll
    for (int o = 16; o > 0; o >>= 1) {
        s1 += __shfl_down_sync(0xffffffffu, s1, o);
        s2 += __shfl_down_sync(0xffffffffu, s2, o);
    }
    if (lane == 0) {
        g_Wh1[gw] = s1;
        g_Wh2[gw] = s2;
    }
}

// ---------------- K1: Wh = h @ W, stored transposed bf16 [b][d][n] ---------
__global__ void k1_wh(const float* __restrict__ h, const float* __restrict__ W) {
    extern __shared__ float sm[];
    float* s_W = sm;
    float* s_h = sm + D_ * D_;
    int c = threadIdx.x;
    int rowbase = blockIdx.x * 32;
    for (int k = 0; k < D_; k++) s_W[k * D_ + c] = W[k * D_ + c];
    for (int r = 0; r < 32; r++) s_h[r * D_ + c] = h[(size_t)(rowbase + r) * D_ + c];
    __syncthreads();

    float acc[32];
#pragma unroll
    for (int r = 0; r < 32; r++) acc[r] = 0.f;
    for (int k = 0; k < D_; k++) {
        float wv = s_W[k * D_ + c];
#pragma unroll
        for (int r = 0; r < 32; r++) acc[r] = fmaf(s_h[r * D_ + k], wv, acc[r]);
    }
    int b = rowbase >> 11;
    int n0 = rowbase & (N_ - 1);
    __nv_bfloat16* dst = g_WhT + ((size_t)(b * D_ + c)) * N_ + n0;
#pragma unroll
    for (int r = 0; r < 32; r += 2) {
        __nv_bfloat162 v = __floats2bfloat162_rn(acc[r], acc[r + 1]);
        *(__nv_bfloat162*)(dst + r) = v;
    }
}

// =============== K3: fused rowsum + attention + warp-MMA PV + residual =====
// grid (16, 8), 512 threads. 128 rows x full d=128 per CTA.
// 16 warps: wr = wid&7 -> rows [wr*16, +16), wc = wid>>3 -> cols [wc*64, +64).
__device__ __forceinline__ uint32_t packbf2(float x, float y) {
    __nv_bfloat162 v = __floats2bfloat162_rn(x, y);
    return *reinterpret_cast<uint32_t*>(&v);
}

__global__ void __launch_bounds__(512, 1) k3_attn(const int* __restrict__ adj,
                                                  const float* __restrict__ h,
                                                  float* __restrict__ out,
                                                  float* __restrict__ attn) {
    extern __shared__ char smem[];
    // layout: [0,2048) s_red, [2048,2560) s_Sinv, [3072,...) 4 tiles (P0,P1,B0,B1)
    float* s_red = (float*)smem;
    float* s_Sinv = (float*)(smem + 2048);
    char* s_P0 = smem + 3072;
    char* s_B0 = s_P0 + 2 * TILE_BYTES;

    int tid = threadIdx.x;
    int lane = tid & 31;
    int wid = tid >> 5;
    int b = blockIdx.y;
    int n0 = blockIdx.x * 128;
    int r = tid & 127;          // row owned for P-compute / pass1
    int q = tid >> 7;           // quarter (0..3)
    int gr = b * N_ + n0 + r;

    const int* adjrow = adj + (size_t)gr * N_;
    float* attrow = attn + (size_t)gr * N_;
    const float* wh2b = g_Wh2 + b * N_;
    const __nv_bfloat16* whTb = g_WhT + (size_t)b * D_ * N_;
    float wh1 = g_Wh1[gr];

    // ---- pass 1: row sums (4 threads per row, 512 cols each) ----
    {
        const int4* a4 = (const int4*)adjrow + q * 128;
        const float4* w4 = (const float4*)wh2b + q * 128;
        float s = 0.f;
#pragma unroll 4
        for (int i = 0; i < 128; i++) {
            int4 m = a4[i];
            float4 v = w4[i];
            float e;
            e = wh1 + v.x; e = fmaxf(e, ALPHA * e); if (m.x) s += __expf(e);
            e = wh1 + v.y; e = fmaxf(e, ALPHA * e); if (m.y) s += __expf(e);
            e = wh1 + v.z; e = fmaxf(e, ALPHA * e); if (m.z) s += __expf(e);
            e = wh1 + v.w; e = fmaxf(e, ALPHA * e); if (m.w) s += __expf(e);
        }
        s_red[tid] = s;
        __syncthreads();
        if (tid < 128)
            s_Sinv[tid] = 1.f / (s_red[tid] + s_red[tid + 128] + s_red[tid + 256] + s_red[tid + 384]);
        __syncthreads();
    }
    float si = s_Sinv[r];

    // MMA role constants
    int wr = wid & 7;           // row group
    int wc = wid >> 3;          // col half
    // A ldmatrix.x4 per-lane byte offset within s_P tile (row-major, PSTR*2 byte rows)
    int a_row = wr * 16 + (lane & 7) + ((lane >> 3) & 1) * 8;
    uint32_t a_off = (uint32_t)(a_row * (PSTR * 2) + (lane >> 4) * 16);
    // B ldmatrix.x2 per-lane byte offset base within s_B tile (only lanes 0-15 matter)
    int b_row = wc * 64 + (lane & 7);
    uint32_t b_off = (uint32_t)(b_row * (PSTR * 2) + ((lane >> 3) & 1) * 16);

    float acc[8][4];
#pragma unroll
    for (int i = 0; i < 8; i++) { acc[i][0] = acc[i][1] = acc[i][2] = acc[i][3] = 0.f; }

    // ---- pass 2 ----
    for (int t = 0; t < NT; t++) {
        int buf = t & 1;
        char* s_P = s_P0 + buf * TILE_BYTES;
        char* s_B = s_B0 + buf * TILE_BYTES;

        // 1) compute P (16 j-values per thread), write attn + s_P (bf16)
        {
            int j0 = t * KT + q * 16;
            uint32_t pk[8];
#pragma unroll
            for (int i = 0; i < 4; i++) {
                int4 m = *(const int4*)(adjrow + j0 + i * 4);
                float4 v = *(const float4*)(wh2b + j0 + i * 4);
                float e, p0, p1, p2, p3;
                e = wh1 + v.x; e = fmaxf(e, ALPHA * e); p0 = m.x ? __expf(e) * si : 0.f;
                e = wh1 + v.y; e = fmaxf(e, ALPHA * e); p1 = m.y ? __expf(e) * si : 0.f;
                e = wh1 + v.z; e = fmaxf(e, ALPHA * e); p2 = m.z ? __expf(e) * si : 0.f;
                e = wh1 + v.w; e = fmaxf(e, ALPHA * e); p3 = m.w ? __expf(e) * si : 0.f;
                *(float4*)(attrow + j0 + i * 4) = make_float4(p0, p1, p2, p3);
                pk[i * 2 + 0] = packbf2(p0, p1);
                pk[i * 2 + 1] = packbf2(p2, p3);
            }
            uint4* pd = (uint4*)(s_P + r * (PSTR * 2) + q * 32);
            pd[0] = make_uint4(pk[0], pk[1], pk[2], pk[3]);
            pd[1] = make_uint4(pk[4], pk[5], pk[6], pk[7]);
        }

        // 2) stage B tile: WhT[b][d][t*64 .. +64) -> s_B (row d, 128B + pad)
        {
#pragma unroll
            for (int z = 0; z < 2; z++) {
                int idx = tid + z * 512;
                int d = idx >> 3, ch = idx & 7;
                *(uint4*)(s_B + d * (PSTR * 2) + ch * 16) =
                    *(const uint4*)((const char*)(whTb + (size_t)d * N_ + t * KT) + ch * 16);
            }
        }
        __syncthreads();

        // 3) MMA: 4 k-steps of m16n8k16
#pragma unroll
        for (int kk = 0; kk < 4; kk++) {
            uint32_t A0, A1, A2, A3;
            {
                uint32_t sa = (uint32_t)__cvta_generic_to_shared(s_P + a_off + kk * 32);
                asm volatile("ldmatrix.sync.aligned.m8n8.x4.shared.b16 {%0,%1,%2,%3}, [%4];\n"
                             : "=r"(A0), "=r"(A1), "=r"(A2), "=r"(A3) : "r"(sa));
            }
#pragma unroll
            for (int nb = 0; nb < 8; nb++) {
                uint32_t B0, B1;
                uint32_t sb = (uint32_t)__cvta_generic_to_shared(
                    s_B + b_off + nb * 8 * (PSTR * 2) + kk * 32);
                asm volatile("ldmatrix.sync.aligned.m8n8.x2.shared.b16 {%0,%1}, [%2];\n"
                             : "=r"(B0), "=r"(B1) : "r"(sb));
                asm volatile("mma.sync.aligned.m16n8k16.row.col.f32.bf16.bf16.f32 "
                             "{%0,%1,%2,%3}, {%4,%5,%6,%7}, {%8,%9}, {%0,%1,%2,%3};\n"
                             : "+f"(acc[nb][0]), "+f"(acc[nb][1]), "+f"(acc[nb][2]), "+f"(acc[nb][3])
                             : "r"(A0), "r"(A1), "r"(A2), "r"(A3), "r"(B0), "r"(B1));
            }
        }
    }

    // ---- epilogue: out = h + h_prime ----
    {
        int row_lo = n0 + wr * 16 + (lane >> 2);
        int gr_lo = b * N_ + row_lo;
        int gr_hi = gr_lo + 8;
        const float* hlo = h + (size_t)gr_lo * D_;
        const float* hhi = h + (size_t)gr_hi * D_;
        float* olo = out + (size_t)gr_lo * D_;
        float* ohi = out + (size_t)gr_hi * D_;
#pragma unroll
        for (int nb = 0; nb < 8; nb++) {
            int c = wc * 64 + nb * 8 + (lane & 3) * 2;
            float2 hv0 = *(const float2*)(hlo + c);
            float2 hv1 = *(const float2*)(hhi + c);
            *(float2*)(olo + c) = make_float2(hv0.x + acc[nb][0], hv0.y + acc[nb][1]);
            *(float2*)(ohi + c) = make_float2(hv1.x + acc[nb][2], hv1.y + acc[nb][3]);
        }
    }
}

// ---------------------------------------------------------------------------
extern "C" void kernel_launch(void* const* d_in, const int* in_sizes, int n_in,
                              void* d_out, int out_size) {
    const float* h   = (const float*)d_in[0];
    const int*   adj = (const int*)d_in[1];
    const float* W   = (const float*)d_in[2];
    const float* a   = (const float*)d_in[3];
    float* out  = (float*)d_out;
    float* attn = out + (size_t)B_ * N_ * D_;

    static int smem_set = 0;
    if (!smem_set) {
        cudaFuncSetAttribute(k1_wh, cudaFuncAttributeMaxDynamicSharedMemorySize, 81920);
        cudaFuncSetAttribute(k3_attn, cudaFuncAttributeMaxDynamicSharedMemorySize,
                             3072 + 4 * TILE_BYTES);
        smem_set = 1;
    }

    k0_wa<<<1, 128>>>(W, a);
    k1b_wh12<<<(B_ * N_) / 8, 256>>>(h);
    k1_wh<<<(B_ * N_) / 32, 128, 81920>>>(h, W);
    k3_attn<<<dim3(N_ / 128, B_), 512, 3072 + 4 * TILE_BYTES>>>(adj, h, out, attn);
}

// round 9
// speedup vs baseline: 1.2028x; 1.2028x over previous
#include <cuda_runtime.h>
#include <cuda_bf16.h>
#include <cstdint>

#define B_ 8
#define N_ 2048
#define D_ 128
#define ALPHA 0.2f
#define KT 64
#define NT (N_ / KT)        // 32 j-tiles
#define PSTR 72             // bf16 elems per smem row (64 + 8 pad) -> 144B stride
#define TILE_BYTES (128 * PSTR * 2)   // 18432 per buffer

// smem layout offsets (bytes) for k3
#define OFF_WH1   0
#define OFF_SINV  512
#define OFF_RED   1024
#define OFF_WH2   1536
#define OFF_TILES (1536 + 8192)              // 9728
#define K3_SMEM   (OFF_TILES + 4 * TILE_BYTES)  // 83456

// ---------------- scratch (device globals; no allocations allowed) ----------
__device__ __align__(16) float g_a1W[D_];
__device__ __align__(16) float g_a2W[D_];
__device__ __align__(16) float g_Wh1[B_ * N_];
__device__ __align__(16) float g_Wh2[B_ * N_];
__device__ __align__(16) __nv_bfloat16 g_WhT[(size_t)B_ * D_ * N_]; // [b][d][n] bf16, 4MB

// ---------------- K0: aW1[k] = sum_c W[k][c]*a[c],  aW2 with a[d:] ----------
__global__ void k0_wa(const float* __restrict__ W, const float* __restrict__ a) {
    int k = threadIdx.x;
    float s1 = 0.f, s2 = 0.f;
    for (int c = 0; c < D_; c++) {
        float wv = W[k * D_ + c];
        s1 = fmaf(wv, a[c], s1);
        s2 = fmaf(wv, a[D_ + c], s2);
    }
    g_a1W[k] = s1;
    g_a2W[k] = s2;
}

// ---------------- K1b: Wh1/Wh2 = h . (W a1/2), one warp per row ------------
__global__ void k1b_wh12(const float* __restrict__ h) {
    int gw = (blockIdx.x * blockDim.x + threadIdx.x) >> 5;
    int lane = threadIdx.x & 31;
    float4 hv = *(const float4*)(h + (size_t)gw * D_ + lane * 4);
    float4 a1 = *(const float4*)(g_a1W + lane * 4);
    float4 a2 = *(const float4*)(g_a2W + lane * 4);
    float s1 = hv.x * a1.x + hv.y * a1.y + hv.z * a1.z + hv.w * a1.w;
    float s2 = hv.x * a2.x + hv.y * a2.y + hv.z * a2.z + hv.w * a2.w;
#pragma unroll
    for (int o = 16; o > 0; o >>= 1) {
        s1 += __shfl_down_sync(0xffffffffu, s1, o);
        s2 += __shfl_down_sync(0xffffffffu, s2, o);
    }
    if (lane == 0) {
        g_Wh1[gw] = s1;
        g_Wh2[gw] = s2;
    }
}

// ---------------- K1: Wh = h @ W, stored transposed bf16 [b][d][n] ---------
__global__ void k1_wh(const float* __restrict__ h, const float* __restrict__ W) {
    extern __shared__ float sm[];
    float* s_W = sm;
    float* s_h = sm + D_ * D_;
    int c = threadIdx.x;
    int rowbase = blockIdx.x * 32;
    for (int k = 0; k < D_; k++) s_W[k * D_ + c] = W[k * D_ + c];
    for (int r = 0; r < 32; r++) s_h[r * D_ + c] = h[(size_t)(rowbase + r) * D_ + c];
    __syncthreads();

    float acc[32];
#pragma unroll
    for (int r = 0; r < 32; r++) acc[r] = 0.f;
    for (int k = 0; k < D_; k++) {
        float wv = s_W[k * D_ + c];
#pragma unroll
        for (int r = 0; r < 32; r++) acc[r] = fmaf(s_h[r * D_ + k], wv, acc[r]);
    }
    int b = rowbase >> 11;
    int n0 = rowbase & (N_ - 1);
    __nv_bfloat16* dst = g_WhT + ((size_t)(b * D_ + c)) * N_ + n0;
#pragma unroll
    for (int r = 0; r < 32; r += 2) {
        __nv_bfloat162 v = __floats2bfloat162_rn(acc[r], acc[r + 1]);
        *(__nv_bfloat162*)(dst + r) = v;
    }
}

// =============== K3: fused rowsum + attention + warp-MMA PV + residual =====
// grid (16, 8), 512 threads, 16 warps. 128 rows x full d=128 per CTA.
// COALESCED mapping: lanes sweep COLUMNS within a row (rows are 8KB apart).
__device__ __forceinline__ uint32_t packbf2(float x, float y) {
    __nv_bfloat162 v = __floats2bfloat162_rn(x, y);
    return *reinterpret_cast<uint32_t*>(&v);
}

__global__ void __launch_bounds__(512, 1) k3_attn(const int* __restrict__ adj,
                                                  const float* __restrict__ h,
                                                  float* __restrict__ out,
                                                  float* __restrict__ attn) {
    extern __shared__ char smem[];
    float* s_wh1 = (float*)(smem + OFF_WH1);
    float* s_Sinv = (float*)(smem + OFF_SINV);
    float* s_red = (float*)(smem + OFF_RED);
    float* s_wh2 = (float*)(smem + OFF_WH2);
    char* s_P0 = smem + OFF_TILES;
    char* s_B0 = s_P0 + 2 * TILE_BYTES;

    int tid = threadIdx.x;
    int lane = tid & 31;
    int wid = tid >> 5;
    int b = blockIdx.y;
    int n0 = blockIdx.x * 128;

    const float* wh2b = g_Wh2 + b * N_;
    const __nv_bfloat16* whTb = g_WhT + (size_t)b * D_ * N_;

    // ---- stage wh2 (2048 floats) + wh1 (128) into smem ----
    *(float4*)(s_wh2 + tid * 4) = *(const float4*)(wh2b + tid * 4);
    if (tid < 128) s_wh1[tid] = g_Wh1[b * N_ + n0 + tid];
    __syncthreads();

    // ---- pass 1: row sums; warp owns 8 rows, lanes sweep columns ----
    {
        int row0 = wid * 8;
#pragma unroll
        for (int i = 0; i < 8; i++) {
            int row = row0 + i;
            float wh1 = s_wh1[row];
            const int4* a4 = (const int4*)(adj + (size_t)(b * N_ + n0 + row) * N_);
            const float4* w4 = (const float4*)s_wh2;
            float s = 0.f;
#pragma unroll 4
            for (int jt = 0; jt < 16; jt++) {
                int j = jt * 32 + lane;
                int4 m = a4[j];
                float4 v = w4[j];
                float e;
                e = wh1 + v.x; e = fmaxf(e, ALPHA * e); if (m.x) s += __expf(e);
                e = wh1 + v.y; e = fmaxf(e, ALPHA * e); if (m.y) s += __expf(e);
                e = wh1 + v.z; e = fmaxf(e, ALPHA * e); if (m.z) s += __expf(e);
                e = wh1 + v.w; e = fmaxf(e, ALPHA * e); if (m.w) s += __expf(e);
            }
#pragma unroll
            for (int o = 16; o > 0; o >>= 1) s += __shfl_xor_sync(0xffffffffu, s, o);
            if (lane == 0) s_red[row] = s;
        }
        __syncthreads();
        if (tid < 128) s_Sinv[tid] = 1.f / s_red[tid];
        __syncthreads();
    }

    // MMA role constants (unchanged layout)
    int wr = wid & 7;           // row group (16 rows)
    int wc = wid >> 3;          // col half (64 cols)
    int a_row = wr * 16 + (lane & 7) + ((lane >> 3) & 1) * 8;
    uint32_t a_off = (uint32_t)(a_row * (PSTR * 2) + (lane >> 4) * 16);
    int b_row = wc * 64 + (lane & 7);
    uint32_t b_off = (uint32_t)(b_row * (PSTR * 2) + ((lane >> 3) & 1) * 16);

    float acc[8][4];
#pragma unroll
    for (int i = 0; i < 8; i++) { acc[i][0] = acc[i][1] = acc[i][2] = acc[i][3] = 0.f; }

    int prow = wid * 8;  // P-compute rows for this warp
    const char* adjb = (const char*)(adj + (size_t)(b * N_ + n0 + prow) * N_);
    float* attb = attn + (size_t)(b * N_ + n0 + prow) * N_;

    // ---- pass 2 ----
    for (int t = 0; t < NT; t++) {
        int buf = t & 1;
        char* s_P = s_P0 + buf * TILE_BYTES;
        char* s_B = s_B0 + buf * TILE_BYTES;
        int j0 = t * KT + lane * 2;

        // 1) compute P: 8 rows x 2 cols per lane; coalesced adj/attn
        {
            float2 w2 = *(const float2*)(s_wh2 + j0);
#pragma unroll
            for (int i = 0; i < 8; i++) {
                int row = prow + i;
                float wh1 = s_wh1[row];
                float si = s_Sinv[row];
                int2 m = *(const int2*)(adjb + ((size_t)i * N_ + j0) * 4);
                float e, p0, p1;
                e = wh1 + w2.x; e = fmaxf(e, ALPHA * e); p0 = m.x ? __expf(e) * si : 0.f;
                e = wh1 + w2.y; e = fmaxf(e, ALPHA * e); p1 = m.y ? __expf(e) * si : 0.f;
                *(float2*)(attb + (size_t)i * N_ + j0) = make_float2(p0, p1);
                *(uint32_t*)(s_P + row * (PSTR * 2) + lane * 4) = packbf2(p0, p1);
            }
        }

        // 2) stage B tile: WhT[b][d][t*64 .. +64) -> s_B (row d, 128B + pad)
#pragma unroll
        for (int z = 0; z < 2; z++) {
            int idx = tid + z * 512;
            int d = idx >> 3, ch = idx & 7;
            *(uint4*)(s_B + d * (PSTR * 2) + ch * 16) =
                *(const uint4*)((const char*)(whTb + (size_t)d * N_ + t * KT) + ch * 16);
        }
        __syncthreads();

        // 3) MMA: 4 k-steps of m16n8k16
#pragma unroll
        for (int kk = 0; kk < 4; kk++) {
            uint32_t A0, A1, A2, A3;
            {
                uint32_t sa = (uint32_t)__cvta_generic_to_shared(s_P + a_off + kk * 32);
                asm volatile("ldmatrix.sync.aligned.m8n8.x4.shared.b16 {%0,%1,%2,%3}, [%4];\n"
                             : "=r"(A0), "=r"(A1), "=r"(A2), "=r"(A3) : "r"(sa));
            }
#pragma unroll
            for (int nb = 0; nb < 8; nb++) {
                uint32_t B0, B1;
                uint32_t sb = (uint32_t)__cvta_generic_to_shared(
                    s_B + b_off + nb * 8 * (PSTR * 2) + kk * 32);
                asm volatile("ldmatrix.sync.aligned.m8n8.x2.shared.b16 {%0,%1}, [%2];\n"
                             : "=r"(B0), "=r"(B1) : "r"(sb));
                asm volatile("mma.sync.aligned.m16n8k16.row.col.f32.bf16.bf16.f32 "
                             "{%0,%1,%2,%3}, {%4,%5,%6,%7}, {%8,%9}, {%0,%1,%2,%3};\n"
                             : "+f"(acc[nb][0]), "+f"(acc[nb][1]), "+f"(acc[nb][2]), "+f"(acc[nb][3])
                             : "r"(A0), "r"(A1), "r"(A2), "r"(A3), "r"(B0), "r"(B1));
            }
        }
    }

    // ---- epilogue: out = h + h_prime ----
    {
        int row_lo = n0 + wr * 16 + (lane >> 2);
        int gr_lo = b * N_ + row_lo;
        int gr_hi = gr_lo + 8;
        const float* hlo = h + (size_t)gr_lo * D_;
        const float* hhi = h + (size_t)gr_hi * D_;
        float* olo = out + (size_t)gr_lo * D_;
        float* ohi = out + (size_t)gr_hi * D_;
#pragma unroll
        for (int nb = 0; nb < 8; nb++) {
            int c = wc * 64 + nb * 8 + (lane & 3) * 2;
            float2 hv0 = *(const float2*)(hlo + c);
            float2 hv1 = *(const float2*)(hhi + c);
            *(float2*)(olo + c) = make_float2(hv0.x + acc[nb][0], hv0.y + acc[nb][1]);
            *(float2*)(ohi + c) = make_float2(hv1.x + acc[nb][2], hv1.y + acc[nb][3]);
        }
    }
}

// ---------------------------------------------------------------------------
extern "C" void kernel_launch(void* const* d_in, const int* in_sizes, int n_in,
                              void* d_out, int out_size) {
    const float* h   = (const float*)d_in[0];
    const int*   adj = (const int*)d_in[1];
    const float* W   = (const float*)d_in[2];
    const float* a   = (const float*)d_in[3];
    float* out  = (float*)d_out;
    float* attn = out + (size_t)B_ * N_ * D_;

    cudaFuncSetAttribute(k1_wh, cudaFuncAttributeMaxDynamicSharedMemorySize, 81920);
    cudaFuncSetAttribute(k3_attn, cudaFuncAttributeMaxDynamicSharedMemorySize, K3_SMEM);

    k0_wa<<<1, 128>>>(W, a);
    k1b_wh12<<<(B_ * N_) / 8, 256>>>(h);
    k1_wh<<<(B_ * N_) / 32, 128, 81920>>>(h, W);
    k3_attn<<<dim3(N_ / 128, B_), 512, K3_SMEM>>>(adj, h, out, attn);
}

// round 10
// speedup vs baseline: 1.2332x; 1.0253x over previous
#include <cuda_runtime.h>
#include <cuda_bf16.h>
#include <cstdint>

#define B_ 8
#define N_ 2048
#define D_ 128
#define ALPHA 0.2f
#define KT 64
#define NT (N_ / KT)        // 32 j-tiles
#define PSTR 72             // bf16 elems per smem row (64 + 8 pad) -> 144B stride
#define TILE_BYTES (128 * PSTR * 2)   // 18432 per buffer

// smem layout offsets (bytes) for k3
#define OFF_WH1   0
#define OFF_SINV  512
#define OFF_RED   1024
#define OFF_WH2   1536
#define OFF_MASK  (1536 + 8192)                  // 9728, 32KB bitmask
#define OFF_TILES (OFF_MASK + 32768)             // 42496
#define K3_SMEM   (OFF_TILES + 4 * TILE_BYTES)   // 116224

// ---------------- scratch (device globals; no allocations allowed) ----------
__device__ __align__(16) float g_a1W[D_];
__device__ __align__(16) float g_a2W[D_];
__device__ __align__(16) float g_Wh1[B_ * N_];
__device__ __align__(16) float g_Wh2[B_ * N_];
__device__ __align__(16) __nv_bfloat16 g_WhT[(size_t)B_ * D_ * N_]; // [b][d][n] bf16, 4MB

// ---------------- K0 ----------
__global__ void k0_wa(const float* __restrict__ W, const float* __restrict__ a) {
    int k = threadIdx.x;
    float s1 = 0.f, s2 = 0.f;
    for (int c = 0; c < D_; c++) {
        float wv = W[k * D_ + c];
        s1 = fmaf(wv, a[c], s1);
        s2 = fmaf(wv, a[D_ + c], s2);
    }
    g_a1W[k] = s1;
    g_a2W[k] = s2;
}

// ---------------- K1b ----------
__global__ void k1b_wh12(const float* __restrict__ h) {
    int gw = (blockIdx.x * blockDim.x + threadIdx.x) >> 5;
    int lane = threadIdx.x & 31;
    float4 hv = *(const float4*)(h + (size_t)gw * D_ + lane * 4);
    float4 a1 = *(const float4*)(g_a1W + lane * 4);
    float4 a2 = *(const float4*)(g_a2W + lane * 4);
    float s1 = hv.x * a1.x + hv.y * a1.y + hv.z * a1.z + hv.w * a1.w;
    float s2 = hv.x * a2.x + hv.y * a2.y + hv.z * a2.z + hv.w * a2.w;
#pragma unroll
    for (int o = 16; o > 0; o >>= 1) {
        s1 += __shfl_down_sync(0xffffffffu, s1, o);
        s2 += __shfl_down_sync(0xffffffffu, s2, o);
    }
    if (lane == 0) {
        g_Wh1[gw] = s1;
        g_Wh2[gw] = s2;
    }
}

// ---------------- K1: Wh = h @ W -> bf16 transposed [b][d][n] ----------
__global__ void k1_wh(const float* __restrict__ h, const float* __restrict__ W) {
    extern __shared__ float sm[];
    float* s_W = sm;
    float* s_h = sm + D_ * D_;
    int c = threadIdx.x;
    int rowbase = blockIdx.x * 32;
    for (int k = 0; k < D_; k++) s_W[k * D_ + c] = W[k * D_ + c];
    for (int r = 0; r < 32; r++) s_h[r * D_ + c] = h[(size_t)(rowbase + r) * D_ + c];
    __syncthreads();

    float acc[32];
#pragma unroll
    for (int r = 0; r < 32; r++) acc[r] = 0.f;
    for (int k = 0; k < D_; k++) {
        float wv = s_W[k * D_ + c];
#pragma unroll
        for (int r = 0; r < 32; r++) acc[r] = fmaf(s_h[r * D_ + k], wv, acc[r]);
    }
    int b = rowbase >> 11;
    int n0 = rowbase & (N_ - 1);
    __nv_bfloat16* dst = g_WhT + ((size_t)(b * D_ + c)) * N_ + n0;
#pragma unroll
    for (int r = 0; r < 32; r += 2) {
        __nv_bfloat162 v = __floats2bfloat162_rn(acc[r], acc[r + 1]);
        *(__nv_bfloat162*)(dst + r) = v;
    }
}

// =============== K3: fused rowsum+mask + attention + warp-MMA + residual ===
__device__ __forceinline__ uint32_t packbf2(float x, float y) {
    __nv_bfloat162 v = __floats2bfloat162_rn(x, y);
    return *reinterpret_cast<uint32_t*>(&v);
}

__global__ void __launch_bounds__(512, 1) k3_attn(const int* __restrict__ adj,
                                                  const float* __restrict__ h,
                                                  float* __restrict__ out,
                                                  float* __restrict__ attn) {
    extern __shared__ char smem[];
    float* s_wh1 = (float*)(smem + OFF_WH1);
    float* s_Sinv = (float*)(smem + OFF_SINV);
    float* s_red = (float*)(smem + OFF_RED);
    float* s_wh2 = (float*)(smem + OFF_WH2);
    uint32_t* s_mask = (uint32_t*)(smem + OFF_MASK);   // [128][64] words
    char* s_P0 = smem + OFF_TILES;
    char* s_B0 = s_P0 + 2 * TILE_BYTES;

    int tid = threadIdx.x;
    int lane = tid & 31;
    int wid = tid >> 5;
    int b = blockIdx.y;
    int n0 = blockIdx.x * 128;

    const float* wh2b = g_Wh2 + b * N_;
    const __nv_bfloat16* whTb = g_WhT + (size_t)b * D_ * N_;

    // ---- stage wh2 + wh1 ----
    *(float4*)(s_wh2 + tid * 4) = *(const float4*)(wh2b + tid * 4);
    if (tid < 128) s_wh1[tid] = g_Wh1[b * N_ + n0 + tid];
    __syncthreads();

    // ---- pass 1: row sums + bitmask build; warp owns 8 rows ----
    {
        int row0 = wid * 8;
#pragma unroll
        for (int i = 0; i < 8; i++) {
            int row = row0 + i;
            float wh1 = s_wh1[row];
            const int4* a4 = (const int4*)(adj + (size_t)(b * N_ + n0 + row) * N_);
            const float4* w4 = (const float4*)s_wh2;
            float s = 0.f;
            uint32_t* mrow = s_mask + row * 64;
#pragma unroll 2
            for (int jt = 0; jt < 16; jt++) {
                int j = jt * 32 + lane;   // int4 index; cols jt*128 + lane*4 ..+4
                int4 m = a4[j];
                float4 v = w4[j];
                float e;
                e = wh1 + v.x; e = fmaxf(e, ALPHA * e); if (m.x) s += __expf(e);
                e = wh1 + v.y; e = fmaxf(e, ALPHA * e); if (m.y) s += __expf(e);
                e = wh1 + v.z; e = fmaxf(e, ALPHA * e); if (m.z) s += __expf(e);
                e = wh1 + v.w; e = fmaxf(e, ALPHA * e); if (m.w) s += __expf(e);
                uint32_t nib = (m.x ? 1u : 0u) | (m.y ? 2u : 0u) |
                               (m.z ? 4u : 0u) | (m.w ? 8u : 0u);
                uint32_t v32 = nib << ((lane & 7) * 4);
                v32 |= __shfl_xor_sync(0xffffffffu, v32, 1);
                v32 |= __shfl_xor_sync(0xffffffffu, v32, 2);
                v32 |= __shfl_xor_sync(0xffffffffu, v32, 4);
                if ((lane & 7) == 0) mrow[jt * 4 + (lane >> 3)] = v32;
            }
#pragma unroll
            for (int o = 16; o > 0; o >>= 1) s += __shfl_xor_sync(0xffffffffu, s, o);
            if (lane == 0) s_red[row] = s;
        }
        __syncthreads();
        if (tid < 128) s_Sinv[tid] = 1.f / s_red[tid];
        __syncthreads();
    }

    // MMA role constants
    int wr = wid & 7;
    int wc = wid >> 3;
    int a_row = wr * 16 + (lane & 7) + ((lane >> 3) & 1) * 8;
    uint32_t a_off = (uint32_t)(a_row * (PSTR * 2) + (lane >> 4) * 16);
    int b_row = wc * 64 + (lane & 7);
    uint32_t b_off = (uint32_t)(b_row * (PSTR * 2) + ((lane >> 3) & 1) * 16);

    float acc[8][4];
#pragma unroll
    for (int i = 0; i < 8; i++) { acc[i][0] = acc[i][1] = acc[i][2] = acc[i][3] = 0.f; }

    int prow = wid * 8;  // P-compute rows for this warp
    float* attb = attn + (size_t)(b * N_ + n0 + prow) * N_;

    // B-prefetch pointers (2 chunks per thread, fixed d/ch)
    int d0 = tid >> 3, ch0 = tid & 7;
    int d1 = (tid + 512) >> 3, ch1 = (tid + 512) & 7;
    const char* bsrc0 = (const char*)(whTb + (size_t)d0 * N_) + ch0 * 16;
    const char* bsrc1 = (const char*)(whTb + (size_t)d1 * N_) + ch1 * 16;
    char* bdst0_base = ((char*)0) + d0 * (PSTR * 2) + ch0 * 16;  // offsets only
    char* bdst1_base = ((char*)0) + d1 * (PSTR * 2) + ch1 * 16;

    uint4 bpf0 = *(const uint4*)bsrc0;   // tile 0 (KT*2 = 128 bytes per tile step)
    uint4 bpf1 = *(const uint4*)bsrc1;

    int mword_idx = lane >> 4;           // which of the tile's 2 words (per row)
    int mbit = (lane * 2) & 31;

    // ---- pass 2 ----
    for (int t = 0; t < NT; t++) {
        int buf = t & 1;
        char* s_P = s_P0 + buf * TILE_BYTES;
        char* s_B = s_B0 + buf * TILE_BYTES;
        int j0 = t * KT + lane * 2;

        // 1) store prefetched B chunk
        *(uint4*)(s_B + (size_t)(bdst0_base - (char*)0)) = bpf0;
        *(uint4*)(s_B + (size_t)(bdst1_base - (char*)0)) = bpf1;

        // 2) compute P from smem mask: 8 rows x 2 cols per lane
        {
            float2 w2 = *(const float2*)(s_wh2 + j0);
#pragma unroll
            for (int i = 0; i < 8; i++) {
                int row = prow + i;
                float wh1 = s_wh1[row];
                float si = s_Sinv[row];
                uint32_t mw = s_mask[row * 64 + t * 2 + mword_idx];
                float e, p0, p1;
                e = wh1 + w2.x; e = fmaxf(e, ALPHA * e);
                p0 = ((mw >> mbit) & 1u) ? __expf(e) * si : 0.f;
                e = wh1 + w2.y; e = fmaxf(e, ALPHA * e);
                p1 = ((mw >> (mbit + 1)) & 1u) ? __expf(e) * si : 0.f;
                *(float2*)(attb + (size_t)i * N_ + j0) = make_float2(p0, p1);
                *(uint32_t*)(s_P + row * (PSTR * 2) + lane * 4) = packbf2(p0, p1);
            }
        }
        __syncthreads();

        // 3) prefetch B for next tile (consumed next iteration)
        if (t + 1 < NT) {
            bpf0 = *(const uint4*)(bsrc0 + (size_t)(t + 1) * KT * 2);
            bpf1 = *(const uint4*)(bsrc1 + (size_t)(t + 1) * KT * 2);
        }

        // 4) MMA: 4 k-steps of m16n8k16
#pragma unroll
        for (int kk = 0; kk < 4; kk++) {
            uint32_t A0, A1, A2, A3;
            {
                uint32_t sa = (uint32_t)__cvta_generic_to_shared(s_P + a_off + kk * 32);
                asm volatile("ldmatrix.sync.aligned.m8n8.x4.shared.b16 {%0,%1,%2,%3}, [%4];\n"
                             : "=r"(A0), "=r"(A1), "=r"(A2), "=r"(A3) : "r"(sa));
            }
#pragma unroll
            for (int nb = 0; nb < 8; nb++) {
                uint32_t B0, B1;
                uint32_t sb = (uint32_t)__cvta_generic_to_shared(
                    s_B + b_off + nb * 8 * (PSTR * 2) + kk * 32);
                asm volatile("ldmatrix.sync.aligned.m8n8.x2.shared.b16 {%0,%1}, [%2];\n"
                             : "=r"(B0), "=r"(B1) : "r"(sb));
                asm volatile("mma.sync.aligned.m16n8k16.row.col.f32.bf16.bf16.f32 "
                             "{%0,%1,%2,%3}, {%4,%5,%6,%7}, {%8,%9}, {%0,%1,%2,%3};\n"
                             : "+f"(acc[nb][0]), "+f"(acc[nb][1]), "+f"(acc[nb][2]), "+f"(acc[nb][3])
                             : "r"(A0), "r"(A1), "r"(A2), "r"(A3), "r"(B0), "r"(B1));
            }
        }
    }

    // ---- epilogue: out = h + h_prime ----
    {
        int row_lo = n0 + wr * 16 + (lane >> 2);
        int gr_lo = b * N_ + row_lo;
        int gr_hi = gr_lo + 8;
        const float* hlo = h + (size_t)gr_lo * D_;
        const float* hhi = h + (size_t)gr_hi * D_;
        float* olo = out + (size_t)gr_lo * D_;
        float* ohi = out + (size_t)gr_hi * D_;
#pragma unroll
        for (int nb = 0; nb < 8; nb++) {
            int c = wc * 64 + nb * 8 + (lane & 3) * 2;
            float2 hv0 = *(const float2*)(hlo + c);
            float2 hv1 = *(const float2*)(hhi + c);
            *(float2*)(olo + c) = make_float2(hv0.x + acc[nb][0], hv0.y + acc[nb][1]);
            *(float2*)(ohi + c) = make_float2(hv1.x + acc[nb][2], hv1.y + acc[nb][3]);
        }
    }
}

// ---------------------------------------------------------------------------
extern "C" void kernel_launch(void* const* d_in, const int* in_sizes, int n_in,
                              void* d_out, int out_size) {
    const float* h   = (const float*)d_in[0];
    const int*   adj = (const int*)d_in[1];
    const float* W   = (const float*)d_in[2];
    const float* a   = (const float*)d_in[3];
    float* out  = (float*)d_out;
    float* attn = out + (size_t)B_ * N_ * D_;

    cudaFuncSetAttribute(k1_wh, cudaFuncAttributeMaxDynamicSharedMemorySize, 81920);
    cudaFuncSetAttribute(k3_attn, cudaFuncAttributeMaxDynamicSharedMemorySize, K3_SMEM);

    k0_wa<<<1, 128>>>(W, a);
    k1b_wh12<<<(B_ * N_) / 8, 256>>>(h);
    k1_wh<<<(B_ * N_) / 32, 128, 81920>>>(h, W);
    k3_attn<<<dim3(N_ / 128, B_), 512, K3_SMEM>>>(adj, h, out, attn);
}

// round 11
// speedup vs baseline: 1.3822x; 1.1208x over previous
#include <cuda_runtime.h>
#include <cuda_bf16.h>
#include <cstdint>

#define B_ 8
#define N_ 2048
#define D_ 128
#define ALPHA 0.2f
#define KT 64
#define NT (N_ / KT)        // 32 j-tiles
#define ROWS 64             // rows per k3 CTA
#define PSTR 72             // bf16 elems per smem row (64 + 8 pad) -> 144B stride
#define P_TILE_BYTES (ROWS * PSTR * 2)   // 9216
#define B_TILE_BYTES (128 * PSTR * 2)    // 18432

// k3 smem layout (bytes)
#define OFF_WH1   0                         // 256
#define OFF_SINV  256                       // 256
#define OFF_RED   512                       // 256
#define OFF_WH2   768                       // 8192
#define OFF_MASK  (768 + 8192)              // 8960, 16KB bitmask (64 rows x 64 words)
#define OFF_TILES (OFF_MASK + 16384)        // 25344
#define K3_SMEM   (OFF_TILES + 2 * P_TILE_BYTES + 2 * B_TILE_BYTES)  // 80640

// ---------------- scratch (device globals; no allocations allowed) ----------
__device__ __align__(16) float g_Wh1[B_ * N_];
__device__ __align__(16) float g_Wh2[B_ * N_];
__device__ __align__(16) __nv_bfloat16 g_WhT[(size_t)B_ * D_ * N_]; // [b][d][n] bf16, 4MB

// ---------------- K1: Wh = h @ W -> bf16 transposed  +  Wh1/Wh2 fused ------
// 512 blocks x 128 threads; 32 rows per block; thread = output column c.
__global__ void k1_wh(const float* __restrict__ h, const float* __restrict__ W,
                      const float* __restrict__ a) {
    extern __shared__ float sm[];
    float* s_W = sm;                 // [128][128]
    float* s_h = sm + D_ * D_;       // [32][128]
    float* s_r1 = s_h + 32 * D_;     // [4][32]
    float* s_r2 = s_r1 + 128;        // [4][32]
    int c = threadIdx.x;
    int lane = c & 31, w = c >> 5;
    int rowbase = blockIdx.x * 32;
    for (int k = 0; k < D_; k++) s_W[k * D_ + c] = W[k * D_ + c];
    for (int r = 0; r < 32; r++) s_h[r * D_ + c] = h[(size_t)(rowbase + r) * D_ + c];
    __syncthreads();

    float acc[32];
#pragma unroll
    for (int r = 0; r < 32; r++) acc[r] = 0.f;
    for (int k = 0; k < D_; k++) {
        float wv = s_W[k * D_ + c];
#pragma unroll
        for (int r = 0; r < 32; r++) acc[r] = fmaf(s_h[r * D_ + k], wv, acc[r]);
    }

    // ---- fused Wh1/Wh2 = Wh @ a[:d], Wh @ a[d:]  (reference order) ----
    float a1 = a[c], a2 = a[D_ + c];
#pragma unroll
    for (int r = 0; r < 32; r++) {
        float v1 = acc[r] * a1;
        float v2 = acc[r] * a2;
#pragma unroll
        for (int o = 16; o > 0; o >>= 1) {
            v1 += __shfl_xor_sync(0xffffffffu, v1, o);
            v2 += __shfl_xor_sync(0xffffffffu, v2, o);
        }
        if (lane == 0) { s_r1[w * 32 + r] = v1; s_r2[w * 32 + r] = v2; }
    }
    __syncthreads();
    if (c < 32)
        g_Wh1[rowbase + c] = s_r1[c] + s_r1[32 + c] + s_r1[64 + c] + s_r1[96 + c];
    else if (c < 64) {
        int r = c - 32;
        g_Wh2[rowbase + r] = s_r2[r] + s_r2[32 + r] + s_r2[64 + r] + s_r2[96 + r];
    }

    // ---- bf16 transposed store ----
    int b = rowbase >> 11;
    int n0 = rowbase & (N_ - 1);
    __nv_bfloat16* dst = g_WhT + ((size_t)(b * D_ + c)) * N_ + n0;
#pragma unroll
    for (int r = 0; r < 32; r += 2) {
        __nv_bfloat162 v = __floats2bfloat162_rn(acc[r], acc[r + 1]);
        *(__nv_bfloat162*)(dst + r) = v;
    }
}

// =============== K3: fused rowsum+mask + attention + warp-MMA + residual ===
// grid (32, 8), 256 threads (8 warps), 64 rows per CTA, 2 CTAs/SM.
__device__ __forceinline__ uint32_t packbf2(float x, float y) {
    __nv_bfloat162 v = __floats2bfloat162_rn(x, y);
    return *reinterpret_cast<uint32_t*>(&v);
}

__global__ void __launch_bounds__(256, 2) k3_attn(const int* __restrict__ adj,
                                                  const float* __restrict__ h,
                                                  float* __restrict__ out,
                                                  float* __restrict__ attn) {
    extern __shared__ char smem[];
    float* s_wh1 = (float*)(smem + OFF_WH1);
    float* s_Sinv = (float*)(smem + OFF_SINV);
    float* s_red = (float*)(smem + OFF_RED);
    float* s_wh2 = (float*)(smem + OFF_WH2);
    uint32_t* s_mask = (uint32_t*)(smem + OFF_MASK);   // [64][64] words
    char* s_P0 = smem + OFF_TILES;
    char* s_B0 = s_P0 + 2 * P_TILE_BYTES;

    int tid = threadIdx.x;
    int lane = tid & 31;
    int wid = tid >> 5;        // 0..7
    int b = blockIdx.y;
    int n0 = blockIdx.x * ROWS;

    const float* wh2b = g_Wh2 + b * N_;
    const __nv_bfloat16* whTb = g_WhT + (size_t)b * D_ * N_;

    // ---- stage wh2 (2048 floats) + wh1 (64) ----
    {
        float4* d4 = (float4*)s_wh2;
        const float4* s4 = (const float4*)wh2b;
        d4[tid] = s4[tid];
        d4[tid + 256] = s4[tid + 256];
    }
    if (tid < ROWS) s_wh1[tid] = g_Wh1[b * N_ + n0 + tid];
    __syncthreads();

    // ---- pass 1: row sums + bitmask build; warp owns 8 rows ----
    {
        int row0 = wid * 8;
#pragma unroll
        for (int i = 0; i < 8; i++) {
            int row = row0 + i;
            float wh1 = s_wh1[row];
            const int4* a4 = (const int4*)(adj + (size_t)(b * N_ + n0 + row) * N_);
            const float4* w4 = (const float4*)s_wh2;
            float s = 0.f;
            uint32_t* mrow = s_mask + row * 64;
#pragma unroll 4
            for (int jt = 0; jt < 16; jt++) {
                int j = jt * 32 + lane;
                int4 m = a4[j];
                float4 v = w4[j];
                float e;
                e = wh1 + v.x; e = fmaxf(e, ALPHA * e); if (m.x) s += __expf(e);
                e = wh1 + v.y; e = fmaxf(e, ALPHA * e); if (m.y) s += __expf(e);
                e = wh1 + v.z; e = fmaxf(e, ALPHA * e); if (m.z) s += __expf(e);
                e = wh1 + v.w; e = fmaxf(e, ALPHA * e); if (m.w) s += __expf(e);
                uint32_t nib = (m.x ? 1u : 0u) | (m.y ? 2u : 0u) |
                               (m.z ? 4u : 0u) | (m.w ? 8u : 0u);
                uint32_t v32 = nib << ((lane & 7) * 4);
                v32 |= __shfl_xor_sync(0xffffffffu, v32, 1);
                v32 |= __shfl_xor_sync(0xffffffffu, v32, 2);
                v32 |= __shfl_xor_sync(0xffffffffu, v32, 4);
                if ((lane & 7) == 0) mrow[jt * 4 + (lane >> 3)] = v32;
            }
#pragma unroll
            for (int o = 16; o > 0; o >>= 1) s += __shfl_xor_sync(0xffffffffu, s, o);
            if (lane == 0) s_red[row] = s;
        }
        __syncthreads();
        if (tid < ROWS) s_Sinv[tid] = 1.f / s_red[tid];
        __syncthreads();
    }

    // MMA role constants: 4 row-groups x 2 col-halves
    int wr = wid & 3;
    int wc = wid >> 2;
    int a_row = wr * 16 + (lane & 7) + ((lane >> 3) & 1) * 8;
    uint32_t a_off = (uint32_t)(a_row * (PSTR * 2) + (lane >> 4) * 16);
    int b_row = wc * 64 + (lane & 7);
    uint32_t b_off = (uint32_t)(b_row * (PSTR * 2) + ((lane >> 3) & 1) * 16);

    float acc[8][4];
#pragma unroll
    for (int i = 0; i < 8; i++) { acc[i][0] = acc[i][1] = acc[i][2] = acc[i][3] = 0.f; }

    int prow = wid * 8;  // P-compute rows for this warp
    float* attb = attn + (size_t)(b * N_ + n0 + prow) * N_;

    // B-prefetch: 4 chunks per thread (128 d-rows x 8 x 16B = 1024 uint4)
    int dd[4], cc[4];
    const char* bsrc[4];
    uint32_t bdst[4];
    uint4 bpf[4];
#pragma unroll
    for (int z = 0; z < 4; z++) {
        int idx = tid + z * 256;
        dd[z] = idx >> 3; cc[z] = idx & 7;
        bsrc[z] = (const char*)(whTb + (size_t)dd[z] * N_) + cc[z] * 16;
        bdst[z] = (uint32_t)(dd[z] * (PSTR * 2) + cc[z] * 16);
        bpf[z] = *(const uint4*)bsrc[z];
    }

    int mword_idx = lane >> 4;
    int mbit = (lane * 2) & 31;

    // ---- pass 2 ----
    for (int t = 0; t < NT; t++) {
        int buf = t & 1;
        char* s_P = s_P0 + buf * P_TILE_BYTES;
        char* s_B = s_B0 + buf * B_TILE_BYTES;
        int j0 = t * KT + lane * 2;

        // 1) store prefetched B chunks
#pragma unroll
        for (int z = 0; z < 4; z++) *(uint4*)(s_B + bdst[z]) = bpf[z];

        // 2) compute P from smem mask: 8 rows x 2 cols per lane
        {
            float2 w2 = *(const float2*)(s_wh2 + j0);
#pragma unroll
            for (int i = 0; i < 8; i++) {
                int row = prow + i;
                float wh1 = s_wh1[row];
                float si = s_Sinv[row];
                uint32_t mw = s_mask[row * 64 + t * 2 + mword_idx];
                float e, p0, p1;
                e = wh1 + w2.x; e = fmaxf(e, ALPHA * e);
                p0 = ((mw >> mbit) & 1u) ? __expf(e) * si : 0.f;
                e = wh1 + w2.y; e = fmaxf(e, ALPHA * e);
                p1 = ((mw >> (mbit + 1)) & 1u) ? __expf(e) * si : 0.f;
                *(float2*)(attb + (size_t)i * N_ + j0) = make_float2(p0, p1);
                *(uint32_t*)(s_P + row * (PSTR * 2) + lane * 4) = packbf2(p0, p1);
            }
        }
        __syncthreads();

        // 3) prefetch B for next tile
        if (t + 1 < NT) {
#pragma unroll
            for (int z = 0; z < 4; z++)
                bpf[z] = *(const uint4*)(bsrc[z] + (size_t)(t + 1) * KT * 2);
        }

        // 4) MMA: 4 k-steps of m16n8k16
#pragma unroll
        for (int kk = 0; kk < 4; kk++) {
            uint32_t A0, A1, A2, A3;
            {
                uint32_t sa = (uint32_t)__cvta_generic_to_shared(s_P + a_off + kk * 32);
                asm volatile("ldmatrix.sync.aligned.m8n8.x4.shared.b16 {%0,%1,%2,%3}, [%4];\n"
                             : "=r"(A0), "=r"(A1), "=r"(A2), "=r"(A3) : "r"(sa));
            }
#pragma unroll
            for (int nb = 0; nb < 8; nb++) {
                uint32_t B0, B1;
                uint32_t sb = (uint32_t)__cvta_generic_to_shared(
                    s_B + b_off + nb * 8 * (PSTR * 2) + kk * 32);
                asm volatile("ldmatrix.sync.aligned.m8n8.x2.shared.b16 {%0,%1}, [%2];\n"
                             : "=r"(B0), "=r"(B1) : "r"(sb));
                asm volatile("mma.sync.aligned.m16n8k16.row.col.f32.bf16.bf16.f32 "
                             "{%0,%1,%2,%3}, {%4,%5,%6,%7}, {%8,%9}, {%0,%1,%2,%3};\n"
                             : "+f"(acc[nb][0]), "+f"(acc[nb][1]), "+f"(acc[nb][2]), "+f"(acc[nb][3])
                             : "r"(A0), "r"(A1), "r"(A2), "r"(A3), "r"(B0), "r"(B1));
            }
        }
    }

    // ---- epilogue: out = h + h_prime ----
    {
        int row_lo = n0 + wr * 16 + (lane >> 2);
        int gr_lo = b * N_ + row_lo;
        int gr_hi = gr_lo + 8;
        const float* hlo = h + (size_t)gr_lo * D_;
        const float* hhi = h + (size_t)gr_hi * D_;
        float* olo = out + (size_t)gr_lo * D_;
        float* ohi = out + (size_t)gr_hi * D_;
#pragma unroll
        for (int nb = 0; nb < 8; nb++) {
            int c = wc * 64 + nb * 8 + (lane & 3) * 2;
            float2 hv0 = *(const float2*)(hlo + c);
            float2 hv1 = *(const float2*)(hhi + c);
            *(float2*)(olo + c) = make_float2(hv0.x + acc[nb][0], hv0.y + acc[nb][1]);
            *(float2*)(ohi + c) = make_float2(hv1.x + acc[nb][2], hv1.y + acc[nb][3]);
        }
    }
}

// ---------------------------------------------------------------------------
extern "C" void kernel_launch(void* const* d_in, const int* in_sizes, int n_in,
                              void* d_out, int out_size) {
    const float* h   = (const float*)d_in[0];
    const int*   adj = (const int*)d_in[1];
    const float* W   = (const float*)d_in[2];
    const float* a   = (const float*)d_in[3];
    float* out  = (float*)d_out;
    float* attn = out + (size_t)B_ * N_ * D_;

    cudaFuncSetAttribute(k1_wh, cudaFuncAttributeMaxDynamicSharedMemorySize, 83968);
    cudaFuncSetAttribute(k3_attn, cudaFuncAttributeMaxDynamicSharedMemorySize, K3_SMEM);

    k1_wh<<<(B_ * N_) / 32, 128, 83968>>>(h, W, a);
    k3_attn<<<dim3(N_ / ROWS, B_), 256, K3_SMEM>>>(adj, h, out, attn);
}

// round 12
// speedup vs baseline: 1.7991x; 1.3016x over previous
#include <cuda_runtime.h>
#include <cuda_bf16.h>
#include <cstdint>

#define B_ 8
#define N_ 2048
#define D_ 128
#define ALPHA 0.2f
#define KT 64
#define NT (N_ / KT)        // 32 j-tiles
#define ROWS 64             // rows per k3 CTA

// k3 smem layout (bytes); P/B tiles are XOR-swizzled, 128B rows, no pad
#define OFF_WH1   0                         // 256
#define OFF_SINV  256                       // 256
#define OFF_RED   512                       // 256
#define OFF_WH2   768                       // 8192
#define OFF_MASK  (768 + 8192)              // 8960: 16KB bitmask (64 rows x 64 words)
#define OFF_P     (OFF_MASK + 16384)        // 25344: 2 x (64 x 128B) = 16384
#define OFF_B     (OFF_P + 16384)           // 41728: 2 x (128 x 128B) = 32768
#define K3_SMEM   (OFF_B + 32768)           // 74496
#define P_BUF_BYTES 8192
#define B_BUF_BYTES 16384

// ---------------- scratch (device globals; no allocations allowed) ----------
__device__ __align__(16) float g_Wh1[B_ * N_];
__device__ __align__(16) float g_Wh2[B_ * N_];
__device__ __align__(16) __nv_bfloat16 g_WhT[(size_t)B_ * D_ * N_]; // [b][d][n] bf16, 4MB

// ========== K1: Wh = h @ W (fp32 register-tiled) + Wh1/Wh2 + bf16 WhT ======
// grid 256, block 256. Block: 64 rows x 128 cols. Thread: 8 rows x 4 cols.
// ty = tid>>5 (rows ty*8..+8), tx = tid&31 (cols tx*4..+4).
__global__ void __launch_bounds__(256) k1_wh(const float* __restrict__ h,
                                             const float* __restrict__ W,
                                             const float* __restrict__ a) {
    __shared__ __align__(16) float s_hT[32][68];    // [k][row], pad 68
    __shared__ __align__(16) float s_W[32][128];    // [k][col]
    __shared__ float s_red1[64 * 33];
    __shared__ float s_red2[64 * 33];

    int tid = threadIdx.x;
    int tx = tid & 31, ty = tid >> 5;
    int rowbase = blockIdx.x * 64;

    float a1v[4], a2v[4];
#pragma unroll
    for (int j = 0; j < 4; j++) {
        a1v[j] = a[tx * 4 + j];
        a2v[j] = a[D_ + tx * 4 + j];
    }

    float acc[8][4];
#pragma unroll
    for (int i = 0; i < 8; i++)
#pragma unroll
        for (int j = 0; j < 4; j++) acc[i][j] = 0.f;

    for (int kc = 0; kc < 4; kc++) {
        // load W chunk: rows kc*32..+32, all 128 cols (1024 float4, 4/thread)
#pragma unroll
        for (int z = 0; z < 4; z++) {
            int idx = tid + z * 256;
            int kr = idx >> 5, c4 = idx & 31;
            *(float4*)&s_W[kr][c4 * 4] =
                *(const float4*)(W + (size_t)(kc * 32 + kr) * D_ + c4 * 4);
        }
        // load h chunk transposed: 64 rows x 32 k (512 float4, 2/thread)
#pragma unroll
        for (int z = 0; z < 2; z++) {
            int idx = tid + z * 256;
            int row = idx >> 3, k4 = (idx & 7) * 4;
            float4 v = *(const float4*)(h + (size_t)(rowbase + row) * D_ + kc * 32 + k4);
            s_hT[k4 + 0][row] = v.x;
            s_hT[k4 + 1][row] = v.y;
            s_hT[k4 + 2][row] = v.z;
            s_hT[k4 + 3][row] = v.w;
        }
        __syncthreads();
#pragma unroll 8
        for (int k = 0; k < 32; k++) {
            float4 h0 = *(float4*)&s_hT[k][ty * 8];
            float4 h1 = *(float4*)&s_hT[k][ty * 8 + 4];
            float4 w0 = *(float4*)&s_W[k][tx * 4];
            float hr[8] = {h0.x, h0.y, h0.z, h0.w, h1.x, h1.y, h1.z, h1.w};
            float wc_[4] = {w0.x, w0.y, w0.z, w0.w};
#pragma unroll
            for (int i = 0; i < 8; i++)
#pragma unroll
                for (int j = 0; j < 4; j++) acc[i][j] = fmaf(hr[i], wc_[j], acc[i][j]);
        }
        __syncthreads();
    }

    // ---- Wh1/Wh2 partials -> smem reduction ----
#pragma unroll
    for (int i = 0; i < 8; i++) {
        float p1 = acc[i][0] * a1v[0] + acc[i][1] * a1v[1] +
                   acc[i][2] * a1v[2] + acc[i][3] * a1v[3];
        float p2 = acc[i][0] * a2v[0] + acc[i][1] * a2v[1] +
                   acc[i][2] * a2v[2] + acc[i][3] * a2v[3];
        s_red1[(ty * 8 + i) * 33 + tx] = p1;
        s_red2[(ty * 8 + i) * 33 + tx] = p2;
    }
    __syncthreads();
    if (tid < 64) {
        float s1 = 0.f, s2 = 0.f;
#pragma unroll
        for (int x = 0; x < 32; x++) {
            s1 += s_red1[tid * 33 + x];
            s2 += s_red2[tid * 33 + x];
        }
        g_Wh1[rowbase + tid] = s1;
        g_Wh2[rowbase + tid] = s2;
    }

    // ---- bf16 transposed store: thread owns 8 consecutive rows per col ----
    int b = rowbase >> 11;
    int n0 = rowbase & (N_ - 1);
#pragma unroll
    for (int j = 0; j < 4; j++) {
        int col = tx * 4 + j;
        uint32_t pk[4];
#pragma unroll
        for (int i = 0; i < 4; i++) {
            __nv_bfloat162 v = __floats2bfloat162_rn(acc[2 * i][j], acc[2 * i + 1][j]);
            pk[i] = *reinterpret_cast<uint32_t*>(&v);
        }
        *(uint4*)(g_WhT + ((size_t)(b * D_ + col)) * N_ + n0 + ty * 8) =
            make_uint4(pk[0], pk[1], pk[2], pk[3]);
    }
}

// =============== K3: fused rowsum+mask + attention + warp-MMA + residual ===
// grid (32, 8), 256 threads (8 warps), 64 rows/CTA. Pipelined: P(t+1)/B(t+1)
// computed between sync and MMA(t). Swizzled smem tiles (128B rows).
__device__ __forceinline__ uint32_t packbf2(float x, float y) {
    __nv_bfloat162 v = __floats2bfloat162_rn(x, y);
    return *reinterpret_cast<uint32_t*>(&v);
}

__global__ void __launch_bounds__(256, 2) k3_attn(const int* __restrict__ adj,
                                                  const float* __restrict__ h,
                                                  float* __restrict__ out,
                                                  float* __restrict__ attn) {
    extern __shared__ char smem[];
    float* s_wh1 = (float*)(smem + OFF_WH1);
    float* s_Sinv = (float*)(smem + OFF_SINV);
    float* s_red = (float*)(smem + OFF_RED);
    float* s_wh2 = (float*)(smem + OFF_WH2);
    uint32_t* s_mask = (uint32_t*)(smem + OFF_MASK);   // [64][64] words

    int tid = threadIdx.x;
    int lane = tid & 31;
    int wid = tid >> 5;        // 0..7
    int b = blockIdx.y;
    int n0 = blockIdx.x * ROWS;

    const float* wh2b = g_Wh2 + b * N_;
    const __nv_bfloat16* whTb = g_WhT + (size_t)b * D_ * N_;

    // ---- stage wh2 (2048 floats) + wh1 (64) ----
    {
        float4* d4 = (float4*)s_wh2;
        const float4* s4 = (const float4*)wh2b;
        d4[tid] = s4[tid];
        d4[tid + 256] = s4[tid + 256];
    }
    if (tid < ROWS) s_wh1[tid] = g_Wh1[b * N_ + n0 + tid];
    __syncthreads();

    // ---- pass 1: row sums + bitmask build; warp owns 8 rows ----
    {
        int row0 = wid * 8;
#pragma unroll
        for (int i = 0; i < 8; i++) {
            int row = row0 + i;
            float wh1 = s_wh1[row];
            const int4* a4 = (const int4*)(adj + (size_t)(b * N_ + n0 + row) * N_);
            const float4* w4 = (const float4*)s_wh2;
            float s = 0.f;
            uint32_t* mrow = s_mask + row * 64;
#pragma unroll 4
            for (int jt = 0; jt < 16; jt++) {
                int j = jt * 32 + lane;
                int4 m = a4[j];
                float4 v = w4[j];
                float e;
                e = wh1 + v.x; e = fmaxf(e, ALPHA * e); if (m.x) s += __expf(e);
                e = wh1 + v.y; e = fmaxf(e, ALPHA * e); if (m.y) s += __expf(e);
                e = wh1 + v.z; e = fmaxf(e, ALPHA * e); if (m.z) s += __expf(e);
                e = wh1 + v.w; e = fmaxf(e, ALPHA * e); if (m.w) s += __expf(e);
                uint32_t nib = (m.x ? 1u : 0u) | (m.y ? 2u : 0u) |
                               (m.z ? 4u : 0u) | (m.w ? 8u : 0u);
                uint32_t v32 = nib << ((lane & 7) * 4);
                v32 |= __shfl_xor_sync(0xffffffffu, v32, 1);
                v32 |= __shfl_xor_sync(0xffffffffu, v32, 2);
                v32 |= __shfl_xor_sync(0xffffffffu, v32, 4);
                if ((lane & 7) == 0) mrow[jt * 4 + (lane >> 3)] = v32;
            }
#pragma unroll
            for (int o = 16; o > 0; o >>= 1) s += __shfl_xor_sync(0xffffffffu, s, o);
            if (lane == 0) s_red[row] = s;
        }
        __syncthreads();
        if (tid < ROWS) s_Sinv[tid] = 1.f / s_red[tid];
        __syncthreads();
    }

    // ---- role constants ----
    int wr = wid & 3;            // row group (16 rows)
    int wc = wid >> 2;           // col half (64 cols)
    uint32_t xmask = (uint32_t)((lane & 7) << 4);          // swizzle mask (shared A/B)
    int a_row = wr * 16 + (lane & 7) + ((lane >> 3) & 1) * 8;
    uint32_t a_rowterm = (uint32_t)(a_row * 128);
    uint32_t a_colbase = (uint32_t)((lane >> 4) * 16);
    uint32_t b_colbase = (uint32_t)(((lane >> 3) & 1) * 16);
    uint32_t b_rowterm[4];
#pragma unroll
    for (int g = 0; g < 4; g++)
        b_rowterm[g] = (uint32_t)((wc * 64 + g * 16 + ((lane >> 4) & 1) * 8 + (lane & 7)) * 128);

    uint32_t sP0 = (uint32_t)__cvta_generic_to_shared(smem + OFF_P);
    uint32_t sB0 = (uint32_t)__cvta_generic_to_shared(smem + OFF_B);

    float acc[8][4];
#pragma unroll
    for (int i = 0; i < 8; i++) { acc[i][0] = acc[i][1] = acc[i][2] = acc[i][3] = 0.f; }

    int prow = wid * 8;  // P-compute rows for this warp
    float* attb = attn + (size_t)(b * N_ + n0 + prow) * N_;
    float wh1r[8], sir[8];
#pragma unroll
    for (int i = 0; i < 8; i++) { wh1r[i] = s_wh1[prow + i]; sir[i] = s_Sinv[prow + i]; }

    // B prefetch setup: 4 uint4 chunks per thread (128 d-rows x 8 chunks)
    const char* bsrc[4];
    uint32_t bdst[4];
    uint4 bpf[4];
#pragma unroll
    for (int z = 0; z < 4; z++) {
        int idx = tid + z * 256;
        int d = idx >> 3, ch = idx & 7;
        bsrc[z] = (const char*)(whTb + (size_t)d * N_) + ch * 16;
        bdst[z] = (uint32_t)(d * 128 + ((ch * 16) ^ ((d & 7) << 4)));
        bpf[z] = *(const uint4*)bsrc[z];
    }

    int mword_idx = lane >> 4;
    int mbit = (lane * 2) & 31;

    // P compute for tile 0 (regs + attn stores only)
    uint32_t pk[8];
    {
        int j0 = lane * 2;
        float2 w2 = *(const float2*)(s_wh2 + j0);
#pragma unroll
        for (int i = 0; i < 8; i++) {
            uint32_t mw = s_mask[(prow + i) * 64 + mword_idx];
            float e, p0, p1;
            e = wh1r[i] + w2.x; e = fmaxf(e, ALPHA * e);
            p0 = ((mw >> mbit) & 1u) ? __expf(e) * sir[i] : 0.f;
            e = wh1r[i] + w2.y; e = fmaxf(e, ALPHA * e);
            p1 = ((mw >> (mbit + 1)) & 1u) ? __expf(e) * sir[i] : 0.f;
            *(float2*)(attb + (size_t)i * N_ + j0) = make_float2(p0, p1);
            pk[i] = packbf2(p0, p1);
        }
    }

    uint32_t p_st_off = (uint32_t)((lane * 4));   // column bytes before swizzle

    // ---- pass 2 (pipelined) ----
    for (int t = 0; t < NT; t++) {
        int buf = t & 1;
        uint32_t sP = sP0 + buf * P_BUF_BYTES;
        uint32_t sB = sB0 + buf * B_BUF_BYTES;

        // 1) commit staged B + P into smem buffers
#pragma unroll
        for (int z = 0; z < 4; z++) {
            asm volatile("st.shared.v4.b32 [%0], {%1,%2,%3,%4};" ::
                         "r"(sB + bdst[z]),
                         "r"(bpf[z].x), "r"(bpf[z].y), "r"(bpf[z].z), "r"(bpf[z].w));
        }
#pragma unroll
        for (int i = 0; i < 8; i++) {
            uint32_t addr = sP + (uint32_t)((prow + i) * 128) + (p_st_off ^ ((uint32_t)i << 4));
            asm volatile("st.shared.b32 [%0], %1;" :: "r"(addr), "r"(pk[i]));
        }
        __syncthreads();

        // 2) prefetch B(t+1) + compute P(t+1) (no smem writes -> overlaps MMA)
        if (t + 1 < NT) {
#pragma unroll
            for (int z = 0; z < 4; z++)
                bpf[z] = *(const uint4*)(bsrc[z] + (size_t)(t + 1) * KT * 2);
            int j0 = (t + 1) * KT + lane * 2;
            float2 w2 = *(const float2*)(s_wh2 + j0);
#pragma unroll
            for (int i = 0; i < 8; i++) {
                uint32_t mw = s_mask[(prow + i) * 64 + (t + 1) * 2 + mword_idx];
                float e, p0, p1;
                e = wh1r[i] + w2.x; e = fmaxf(e, ALPHA * e);
                p0 = ((mw >> mbit) & 1u) ? __expf(e) * sir[i] : 0.f;
                e = wh1r[i] + w2.y; e = fmaxf(e, ALPHA * e);
                p1 = ((mw >> (mbit + 1)) & 1u) ? __expf(e) * sir[i] : 0.f;
                *(float2*)(attb + (size_t)i * N_ + j0) = make_float2(p0, p1);
                pk[i] = packbf2(p0, p1);
            }
        }

        // 3) MMA(t): per k-step, prehoist A (x4) + 4x B (x4), then 8 MMAs
#pragma unroll
        for (int kk = 0; kk < 4; kk++) {
            uint32_t A0, A1, A2, A3;
            {
                uint32_t sa = sP + a_rowterm + (((uint32_t)(kk * 32) + a_colbase) ^ xmask);
                asm volatile("ldmatrix.sync.aligned.m8n8.x4.shared.b16 {%0,%1,%2,%3}, [%4];\n"
                             : "=r"(A0), "=r"(A1), "=r"(A2), "=r"(A3) : "r"(sa));
            }
            uint32_t Bf[16];
#pragma unroll
            for (int g = 0; g < 4; g++) {
                uint32_t sb = sB + b_rowterm[g] + (((uint32_t)(kk * 32) + b_colbase) ^ xmask);
                asm volatile("ldmatrix.sync.aligned.m8n8.x4.shared.b16 {%0,%1,%2,%3}, [%4];\n"
                             : "=r"(Bf[g * 4]), "=r"(Bf[g * 4 + 1]),
                               "=r"(Bf[g * 4 + 2]), "=r"(Bf[g * 4 + 3]) : "r"(sb));
            }
#pragma unroll
            for (int nb = 0; nb < 8; nb++) {
                int g = nb >> 1, hf = nb & 1;
                asm volatile("mma.sync.aligned.m16n8k16.row.col.f32.bf16.bf16.f32 "
                             "{%0,%1,%2,%3}, {%4,%5,%6,%7}, {%8,%9}, {%0,%1,%2,%3};\n"
                             : "+f"(acc[nb][0]), "+f"(acc[nb][1]), "+f"(acc[nb][2]), "+f"(acc[nb][3])
                             : "r"(A0), "r"(A1), "r"(A2), "r"(A3),
                               "r"(Bf[g * 4 + hf * 2]), "r"(Bf[g * 4 + hf * 2 + 1]));
            }
        }
    }

    // ---- epilogue: out = h + h_prime ----
    {
        int row_lo = n0 + wr * 16 + (lane >> 2);
        int gr_lo = b * N_ + row_lo;
        int gr_hi = gr_lo + 8;
        const float* hlo = h + (size_t)gr_lo * D_;
        const float* hhi = h + (size_t)gr_hi * D_;
        float* olo = out + (size_t)gr_lo * D_;
        float* ohi = out + (size_t)gr_hi * D_;
#pragma unroll
        for (int nb = 0; nb < 8; nb++) {
            int c = wc * 64 + nb * 8 + (lane & 3) * 2;
            float2 hv0 = *(const float2*)(hlo + c);
            float2 hv1 = *(const float2*)(hhi + c);
            *(float2*)(olo + c) = make_float2(hv0.x + acc[nb][0], hv0.y + acc[nb][1]);
            *(float2*)(ohi + c) = make_float2(hv1.x + acc[nb][2], hv1.y + acc[nb][3]);
        }
    }
}

// ---------------------------------------------------------------------------
extern "C" void kernel_launch(void* const* d_in, const int* in_sizes, int n_in,
                              void* d_out, int out_size) {
    const float* h   = (const float*)d_in[0];
    const int*   adj = (const int*)d_in[1];
    const float* W   = (const float*)d_in[2];
    const float* a   = (const float*)d_in[3];
    float* out  = (float*)d_out;
    float* attn = out + (size_t)B_ * N_ * D_;

    cudaFuncSetAttribute(k3_attn, cudaFuncAttributeMaxDynamicSharedMemorySize, K3_SMEM);

    k1_wh<<<(B_ * N_) / 64, 256>>>(h, W, a);
    k3_attn<<<dim3(N_ / ROWS, B_), 256, K3_SMEM>>>(adj, h, out, attn);
}

// round 14
// speedup vs baseline: 1.8641x; 1.0361x over previous
#include <cuda_runtime.h>
#include <cuda_bf16.h>
#include <cstdint>

#define B_ 8
#define N_ 2048
#define D_ 128
#define ALPHA 0.2f
#define KT 64
#define NT (N_ / KT)        // 32 j-tiles
#define ROWS 64             // rows per k3 CTA

// k3 smem layout (bytes); P/B tiles are XOR-swizzled, 128B rows, no pad
#define OFF_WH1   0                         // 256
#define OFF_SINV  256                       // 256
#define OFF_RED   512                       // 256
#define OFF_WH2   768                       // 8192
#define OFF_MASK  (768 + 8192)              // 8960: 16KB bitmask (64 rows x 64 words)
#define OFF_P     (OFF_MASK + 16384)        // 25344: 2 x (64 x 128B) = 16384
#define OFF_B     (OFF_P + 16384)           // 41728: 2 x (128 x 128B) = 32768
#define K3_SMEM   (OFF_B + 32768)           // 74496
#define P_BUF_BYTES 8192
#define B_BUF_BYTES 16384

#define CP_ASYNC16(dst, src) \
    asm volatile("cp.async.cg.shared.global [%0], [%1], 16;" :: "r"(dst), "l"(src))
#define CP_COMMIT() asm volatile("cp.async.commit_group;" ::: "memory")
#define CP_WAIT0()  asm volatile("cp.async.wait_group 0;" ::: "memory")

// ---------------- scratch (device globals; no allocations allowed) ----------
__device__ __align__(16) float g_Wh1[B_ * N_];
__device__ __align__(16) float g_Wh2[B_ * N_];
__device__ __align__(16) __nv_bfloat16 g_WhT[(size_t)B_ * D_ * N_]; // [b][d][n] bf16, 4MB

// ========== K1: Wh = h @ W (fp32 register-tiled) + Wh1/Wh2 + bf16 WhT ======
__global__ void __launch_bounds__(256) k1_wh(const float* __restrict__ h,
                                             const float* __restrict__ W,
                                             const float* __restrict__ a) {
    __shared__ __align__(16) float s_hT[32][68];
    __shared__ __align__(16) float s_W[32][128];
    __shared__ float s_red1[64 * 33];
    __shared__ float s_red2[64 * 33];

    int tid = threadIdx.x;
    int tx = tid & 31, ty = tid >> 5;
    int rowbase = blockIdx.x * 64;

    float a1v[4], a2v[4];
#pragma unroll
    for (int j = 0; j < 4; j++) {
        a1v[j] = a[tx * 4 + j];
        a2v[j] = a[D_ + tx * 4 + j];
    }

    float acc[8][4];
#pragma unroll
    for (int i = 0; i < 8; i++)
#pragma unroll
        for (int j = 0; j < 4; j++) acc[i][j] = 0.f;

    for (int kc = 0; kc < 4; kc++) {
#pragma unroll
        for (int z = 0; z < 4; z++) {
            int idx = tid + z * 256;
            int kr = idx >> 5, c4 = idx & 31;
            *(float4*)&s_W[kr][c4 * 4] =
                *(const float4*)(W + (size_t)(kc * 32 + kr) * D_ + c4 * 4);
        }
#pragma unroll
        for (int z = 0; z < 2; z++) {
            int idx = tid + z * 256;
            int row = idx >> 3, k4 = (idx & 7) * 4;
            float4 v = *(const float4*)(h + (size_t)(rowbase + row) * D_ + kc * 32 + k4);
            s_hT[k4 + 0][row] = v.x;
            s_hT[k4 + 1][row] = v.y;
            s_hT[k4 + 2][row] = v.z;
            s_hT[k4 + 3][row] = v.w;
        }
        __syncthreads();
#pragma unroll 8
        for (int k = 0; k < 32; k++) {
            float4 h0 = *(float4*)&s_hT[k][ty * 8];
            float4 h1 = *(float4*)&s_hT[k][ty * 8 + 4];
            float4 w0 = *(float4*)&s_W[k][tx * 4];
            float hr[8] = {h0.x, h0.y, h0.z, h0.w, h1.x, h1.y, h1.z, h1.w};
            float wc_[4] = {w0.x, w0.y, w0.z, w0.w};
#pragma unroll
            for (int i = 0; i < 8; i++)
#pragma unroll
                for (int j = 0; j < 4; j++) acc[i][j] = fmaf(hr[i], wc_[j], acc[i][j]);
        }
        __syncthreads();
    }

#pragma unroll
    for (int i = 0; i < 8; i++) {
        float p1 = acc[i][0] * a1v[0] + acc[i][1] * a1v[1] +
                   acc[i][2] * a1v[2] + acc[i][3] * a1v[3];
        float p2 = acc[i][0] * a2v[0] + acc[i][1] * a2v[1] +
                   acc[i][2] * a2v[2] + acc[i][3] * a2v[3];
        s_red1[(ty * 8 + i) * 33 + tx] = p1;
        s_red2[(ty * 8 + i) * 33 + tx] = p2;
    }
    __syncthreads();
    if (tid < 64) {
        float s1 = 0.f, s2 = 0.f;
#pragma unroll
        for (int x = 0; x < 32; x++) {
            s1 += s_red1[tid * 33 + x];
            s2 += s_red2[tid * 33 + x];
        }
        g_Wh1[rowbase + tid] = s1;
        g_Wh2[rowbase + tid] = s2;
    }

    int b = rowbase >> 11;
    int n0 = rowbase & (N_ - 1);
#pragma unroll
    for (int j = 0; j < 4; j++) {
        int col = tx * 4 + j;
        uint32_t pk[4];
#pragma unroll
        for (int i = 0; i < 4; i++) {
            __nv_bfloat162 v = __floats2bfloat162_rn(acc[2 * i][j], acc[2 * i + 1][j]);
            pk[i] = *reinterpret_cast<uint32_t*>(&v);
        }
        *(uint4*)(g_WhT + ((size_t)(b * D_ + col)) * N_ + n0 + ty * 8) =
            make_uint4(pk[0], pk[1], pk[2], pk[3]);
    }
}

// =============== K3: fused rowsum+mask + attention + warp-MMA + residual ===
__device__ __forceinline__ uint32_t packbf2(float x, float y) {
    __nv_bfloat162 v = __floats2bfloat162_rn(x, y);
    return *reinterpret_cast<uint32_t*>(&v);
}

__global__ void __launch_bounds__(256, 2) k3_attn(const int* __restrict__ adj,
                                                  const float* __restrict__ h,
                                                  float* __restrict__ out,
                                                  float* __restrict__ attn) {
    extern __shared__ char smem[];
    float* s_wh1 = (float*)(smem + OFF_WH1);
    float* s_Sinv = (float*)(smem + OFF_SINV);
    float* s_red = (float*)(smem + OFF_RED);
    float* s_wh2 = (float*)(smem + OFF_WH2);
    uint32_t* s_mask = (uint32_t*)(smem + OFF_MASK);   // [64][64] words

    int tid = threadIdx.x;
    int lane = tid & 31;
    int wid = tid >> 5;        // 0..7
    int b = blockIdx.y;
    int n0 = blockIdx.x * ROWS;

    const float* wh2b = g_Wh2 + b * N_;
    const __nv_bfloat16* whTb = g_WhT + (size_t)b * D_ * N_;

    // ---- stage wh2 (2048 floats) + wh1 (64) ----
    {
        float4* d4 = (float4*)s_wh2;
        const float4* s4 = (const float4*)wh2b;
        d4[tid] = s4[tid];
        d4[tid + 256] = s4[tid + 256];
    }
    if (tid < ROWS) s_wh1[tid] = g_Wh1[b * N_ + n0 + tid];
    __syncthreads();

    // ---- pass 1: row sums + bitmask build; warp owns 8 rows ----
    {
        int row0 = wid * 8;
#pragma unroll
        for (int i = 0; i < 8; i++) {
            int row = row0 + i;
            float wh1 = s_wh1[row];
            const int4* a4 = (const int4*)(adj + (size_t)(b * N_ + n0 + row) * N_);
            const float4* w4 = (const float4*)s_wh2;
            float s = 0.f;
            uint32_t* mrow = s_mask + row * 64;
#pragma unroll 4
            for (int jt = 0; jt < 16; jt++) {
                int j = jt * 32 + lane;
                int4 m = a4[j];
                float4 v = w4[j];
                float e;
                e = wh1 + v.x; e = fmaxf(e, ALPHA * e); if (m.x) s += __expf(e);
                e = wh1 + v.y; e = fmaxf(e, ALPHA * e); if (m.y) s += __expf(e);
                e = wh1 + v.z; e = fmaxf(e, ALPHA * e); if (m.z) s += __expf(e);
                e = wh1 + v.w; e = fmaxf(e, ALPHA * e); if (m.w) s += __expf(e);
                uint32_t nib = (m.x ? 1u : 0u) | (m.y ? 2u : 0u) |
                               (m.z ? 4u : 0u) | (m.w ? 8u : 0u);
                uint32_t v32 = nib << ((lane & 7) * 4);
                v32 |= __shfl_xor_sync(0xffffffffu, v32, 1);
                v32 |= __shfl_xor_sync(0xffffffffu, v32, 2);
                v32 |= __shfl_xor_sync(0xffffffffu, v32, 4);
                if ((lane & 7) == 0) mrow[jt * 4 + (lane >> 3)] = v32;
            }
#pragma unroll
            for (int o = 16; o > 0; o >>= 1) s += __shfl_xor_sync(0xffffffffu, s, o);
            if (lane == 0) s_red[row] = s;
        }
        __syncthreads();
        if (tid < ROWS) s_Sinv[tid] = 1.f / s_red[tid];
        __syncthreads();
    }

    // ---- role constants ----
    int wr = wid & 3;            // row group (16 rows)
    int wc = wid >> 2;           // col half (64 cols)
    uint32_t xmask = (uint32_t)((lane & 7) << 4);
    int a_row = wr * 16 + (lane & 7) + ((lane >> 3) & 1) * 8;
    uint32_t a_rowterm = (uint32_t)(a_row * 128);
    uint32_t a_colbase = (uint32_t)((lane >> 4) * 16);
    uint32_t b_colbase = (uint32_t)(((lane >> 3) & 1) * 16);
    uint32_t b_rowterm[4];
#pragma unroll
    for (int g = 0; g < 4; g++)
        b_rowterm[g] = (uint32_t)((wc * 64 + g * 16 + ((lane >> 4) & 1) * 8 + (lane & 7)) * 128);

    uint32_t sP0 = (uint32_t)__cvta_generic_to_shared(smem + OFF_P);
    uint32_t sB0 = (uint32_t)__cvta_generic_to_shared(smem + OFF_B);

    float acc[8][4];
#pragma unroll
    for (int i = 0; i < 8; i++) { acc[i][0] = acc[i][1] = acc[i][2] = acc[i][3] = 0.f; }

    // ---- P-compute mapping: lane = (cl 0-15: 4 cols) x (rh 0-1: row within pair)
    int prow = wid * 8;
    int cl = lane & 15;
    int rh = lane >> 4;
    float* attp[4];
    float wh1r[4], sir[4];
    uint32_t poff[4];            // P smem store offsets (row*128 + swizzled col)
#pragma unroll
    for (int i = 0; i < 4; i++) {
        int rloc = i * 2 + rh;
        int row = prow + rloc;
        attp[i] = attn + (size_t)(b * N_ + n0 + row) * N_;
        wh1r[i] = s_wh1[row];
        sir[i] = s_Sinv[row];
        poff[i] = (uint32_t)(row * 128 + ((cl * 8) ^ (rloc << 4)));
    }
    int mword = cl >> 3;         // word within tile's 2 words
    int mshift = (cl & 7) * 4;   // bit group within word

    // B cp.async setup: 4 x 16B chunks per thread
    const char* bsrc[4];
    uint32_t bdst[4];
#pragma unroll
    for (int z = 0; z < 4; z++) {
        int idx = tid + z * 256;
        int d = idx >> 3, ch = idx & 7;
        bsrc[z] = (const char*)(whTb + (size_t)d * N_) + ch * 16;
        bdst[z] = (uint32_t)(d * 128 + ((ch * 16) ^ ((d & 7) << 4)));
    }

    uint32_t pk[8];

#define COMPUTE_P(T)                                                            \
    {                                                                           \
        int j0 = (T) * KT + cl * 4;                                             \
        float4 w4 = *(const float4*)(s_wh2 + j0);                               \
        _Pragma("unroll")                                                       \
        for (int i = 0; i < 4; i++) {                                           \
            uint32_t bits = s_mask[(prow + i * 2 + rh) * 64 + (T) * 2 + mword]  \
                            >> mshift;                                          \
            float e0 = wh1r[i] + w4.x; e0 = fmaxf(e0, ALPHA * e0);              \
            float e1 = wh1r[i] + w4.y; e1 = fmaxf(e1, ALPHA * e1);              \
            float e2 = wh1r[i] + w4.z; e2 = fmaxf(e2, ALPHA * e2);              \
            float e3 = wh1r[i] + w4.w; e3 = fmaxf(e3, ALPHA * e3);              \
            float p0 = (bits & 1u) ? __expf(e0) * sir[i] : 0.f;                 \
            float p1 = (bits & 2u) ? __expf(e1) * sir[i] : 0.f;                 \
            float p2 = (bits & 4u) ? __expf(e2) * sir[i] : 0.f;                 \
            float p3 = (bits & 8u) ? __expf(e3) * sir[i] : 0.f;                 \
            *(float4*)(attp[i] + j0) = make_float4(p0, p1, p2, p3);             \
            pk[i * 2 + 0] = packbf2(p0, p1);                                    \
            pk[i * 2 + 1] = packbf2(p2, p3);                                    \
        }                                                                       \
    }

    // prologue: B(0) in flight, P(0) in registers
#pragma unroll
    for (int z = 0; z < 4; z++) CP_ASYNC16(sB0 + bdst[z], bsrc[z]);
    CP_COMMIT();
    COMPUTE_P(0);

    // ---- pass 2 (pipelined) ----
    for (int t = 0; t < NT; t++) {
        int buf = t & 1;
        uint32_t sP = sP0 + buf * P_BUF_BYTES;
        uint32_t sB = sB0 + buf * B_BUF_BYTES;

        CP_WAIT0();   // B(t) landed (this thread's chunks)
#pragma unroll
        for (int i = 0; i < 4; i++) {
            asm volatile("st.shared.v2.b32 [%0], {%1,%2};" ::
                         "r"(sP + poff[i]), "r"(pk[i * 2]), "r"(pk[i * 2 + 1]));
        }
        __syncthreads();  // B(t), P(t) visible to all warps

        if (t + 1 < NT) {
            uint32_t sBn = sB0 + ((t + 1) & 1) * B_BUF_BYTES;
            const char* srcadd = (const char*)0 + (size_t)(t + 1) * KT * 2;
#pragma unroll
            for (int z = 0; z < 4; z++)
                CP_ASYNC16(sBn + bdst[z], bsrc[z] + (size_t)(srcadd - (const char*)0));
            CP_COMMIT();
            COMPUTE_P(t + 1);
        }

        // MMA(t): per k-step, prehoist A (x4) + 4x B (x4), then 8 MMAs
#pragma unroll
        for (int kk = 0; kk < 4; kk++) {
            uint32_t A0, A1, A2, A3;
            {
                uint32_t sa = sP + a_rowterm + (((uint32_t)(kk * 32) + a_colbase) ^ xmask);
                asm volatile("ldmatrix.sync.aligned.m8n8.x4.shared.b16 {%0,%1,%2,%3}, [%4];\n"
                             : "=r"(A0), "=r"(A1), "=r"(A2), "=r"(A3) : "r"(sa));
            }
            uint32_t Bf[16];
#pragma unroll
            for (int g = 0; g < 4; g++) {
                uint32_t sb = sB + b_rowterm[g] + (((uint32_t)(kk * 32) + b_colbase) ^ xmask);
                asm volatile("ldmatrix.sync.aligned.m8n8.x4.shared.b16 {%0,%1,%2,%3}, [%4];\n"
                             : "=r"(Bf[g * 4]), "=r"(Bf[g * 4 + 1]),
                               "=r"(Bf[g * 4 + 2]), "=r"(Bf[g * 4 + 3]) : "r"(sb));
            }
#pragma unroll
            for (int nb = 0; nb < 8; nb++) {
                int g = nb >> 1, hf = nb & 1;
                asm volatile("mma.sync.aligned.m16n8k16.row.col.f32.bf16.bf16.f32 "
                             "{%0,%1,%2,%3}, {%4,%5,%6,%7}, {%8,%9}, {%0,%1,%2,%3};\n"
                             : "+f"(acc[nb][0]), "+f"(acc[nb][1]), "+f"(acc[nb][2]), "+f"(acc[nb][3])
                             : "r"(A0), "r"(A1), "r"(A2), "r"(A3),
                               "r"(Bf[g * 4 + hf * 2]), "r"(Bf[g * 4 + hf * 2 + 1]));
            }
        }
    }

    // ---- epilogue: out = h + h_prime ----
    {
        int row_lo = n0 + wr * 16 + (lane >> 2);
        int gr_lo = b * N_ + row_lo;
        int gr_hi = gr_lo + 8;
        const float* hlo = h + (size_t)gr_lo * D_;
        const float* hhi = h + (size_t)gr_hi * D_;
        float* olo = out + (size_t)gr_lo * D_;
        float* ohi = out + (size_t)gr_hi * D_;
#pragma unroll
        for (int nb = 0; nb < 8; nb++) {
            int c = wc * 64 + nb * 8 + (lane & 3) * 2;
            float2 hv0 = *(const float2*)(hlo + c);
            float2 hv1 = *(const float2*)(hhi + c);
            *(float2*)(olo + c) = make_float2(hv0.x + acc[nb][0], hv0.y + acc[nb][1]);
            *(float2*)(ohi + c) = make_float2(hv1.x + acc[nb][2], hv1.y + acc[nb][3]);
        }
    }
}

// ---------------------------------------------------------------------------
extern "C" void kernel_launch(void* const* d_in, const int* in_sizes, int n_in,
                              void* d_out, int out_size) {
    const float* h   = (const float*)d_in[0];
    const int*   adj = (const int*)d_in[1];
    const float* W   = (const float*)d_in[2];
    const float* a   = (const float*)d_in[3];
    float* out  = (float*)d_out;
    float* attn = out + (size_t)B_ * N_ * D_;

    cudaFuncSetAttribute(k3_attn, cudaFuncAttributeMaxDynamicSharedMemorySize, K3_SMEM);

    k1_wh<<<(B_ * N_) / 64, 256>>>(h, W, a);
    k3_attn<<<dim3(N_ / ROWS, B_), 256, K3_SMEM>>>(adj, h, out, attn);
}